// round 17
// baseline (speedup 1.0000x reference)
#include <cuda_runtime.h>
#include <cuda_fp16.h>
#include <cstdint>

// Dims fixed: B=4, S=256, D_MODEL=2048, H=256, HEAD_DIM=8; M = B*S = 1024.
#define M_DIM 1024
#define N_DIM 2048
#define K_DIM 2048
#define HEADS 256
#define WSZ   ((size_t)K_DIM * N_DIM)

// ---------------- scratch ----------------
__device__ float  g_q  [M_DIM * N_DIM];       // q; later: o-partial 0
__device__ float  g_k  [M_DIM * N_DIM];       // k; later: o-partial 1
__device__ float  g_v  [M_DIM * N_DIM];
__device__ __half g_att[M_DIM * N_DIM];       // attention out, fp16 (k-contig)
__device__ __half g_xh [M_DIM * K_DIM];       // x as fp16 (k-contig)
__device__ __half g_whT[4 * WSZ];             // W^T as fp16: [z][n][k] (k-contig)
__device__ float  g_zero[N_DIM];              // zero bias (zero-initialized)

// ---------------- helpers ----------------
__device__ __forceinline__ uint32_t pack2(float lo, float hi) {
    __half2 h = __floats2half2_rn(lo, hi);
    return *(uint32_t*)&h;
}
__device__ __forceinline__ uint32_t smem_u32(const void* p) {
    uint32_t a;
    asm("{ .reg .u64 t; cvta.to.shared.u64 t, %1; cvt.u32.u64 %0, t; }" : "=r"(a) : "l"(p));
    return a;
}
#define CP_ASYNC16(dst, src) \
    asm volatile("cp.async.cg.shared.global [%0], [%1], 16;" :: "r"(dst), "l"(src))
#define CP_COMMIT() asm volatile("cp.async.commit_group;" ::: "memory")
#define CP_WAIT0()  asm volatile("cp.async.wait_group 0;"  ::: "memory")
#define CP_WAIT1()  asm volatile("cp.async.wait_group 1;"  ::: "memory")
#define CP_WAIT2()  asm volatile("cp.async.wait_group 2;"  ::: "memory")

#define LDSM4(r0, r1, r2, r3, addr)                                   \
    asm volatile("ldmatrix.sync.aligned.m8n8.x4.shared.b16 "          \
                 "{%0,%1,%2,%3}, [%4];"                                \
                 : "=r"(r0), "=r"(r1), "=r"(r2), "=r"(r3) : "r"(addr))

__device__ __forceinline__ void mma_f16(float* c,
                                        unsigned a0, unsigned a1, unsigned a2, unsigned a3,
                                        unsigned b0, unsigned b1)
{
    asm volatile(
        "mma.sync.aligned.m16n8k16.row.col.f32.f16.f16.f32 "
        "{%0,%1,%2,%3}, {%4,%5,%6,%7}, {%8,%9}, {%0,%1,%2,%3};\n"
        : "+f"(c[0]), "+f"(c[1]), "+f"(c[2]), "+f"(c[3])
        : "r"(a0), "r"(a1), "r"(a2), "r"(a3), "r"(b0), "r"(b1));
}

// f32x2 packed fp32 math (PTX sm_100+)
typedef unsigned long long ull;
__device__ __forceinline__ ull pk2f(float x, float y) {
    ull r; asm("mov.b64 %0, {%1, %2};" : "=l"(r) : "f"(x), "f"(y)); return r;
}
#define FMAX2(d, a, b, c) \
    asm("fma.rn.f32x2 %0, %1, %2, %3;" : "=l"(d) : "l"(a), "l"(b), "l"(c))
#define MULX2(d, a, b) \
    asm("mul.rn.f32x2 %0, %1, %2;" : "=l"(d) : "l"(a), "l"(b))
#define UPKX2(x, y, v) \
    asm("mov.b64 {%0, %1}, %2;" : "=f"(x), "=f"(y) : "l"(v))

// ---------------- prepass: x -> fp16; W -> fp16 transposed [n][k] ----------------
__global__ void cvt_all(const float* __restrict__ x,
                        const float* __restrict__ Wq, const float* __restrict__ Wk,
                        const float* __restrict__ Wv, const float* __restrict__ Wo)
{
    __shared__ float s[64][65];
    const int tx = threadIdx.x, ty = threadIdx.y;   // (32, 8)
    const int tid = ty * 32 + tx;
    if (blockIdx.y < 4) {
        const float* W = (blockIdx.y == 0) ? Wq : (blockIdx.y == 1) ? Wk
                       : (blockIdx.y == 2) ? Wv : Wo;
        __half* D = g_whT + (size_t)blockIdx.y * WSZ;
        const int kb = (blockIdx.x & 31) * 64;
        const int nb = (blockIdx.x >> 5) * 64;
        #pragma unroll
        for (int j = 0; j < 8; j++) {
            const int r = ty + j * 8;
            const float* src = W + (size_t)(kb + r) * N_DIM + nb;
            s[r][tx]      = src[tx];
            s[r][tx + 32] = src[tx + 32];
        }
        __syncthreads();
        #pragma unroll
        for (int i = 0; i < 2; i++) {
            const int u  = tid * 2 + i;
            const int n  = u >> 3;
            const int ch = (u & 7) * 8;
            uint4 o;
            o.x = pack2(s[ch + 0][n], s[ch + 1][n]);
            o.y = pack2(s[ch + 2][n], s[ch + 3][n]);
            o.z = pack2(s[ch + 4][n], s[ch + 5][n]);
            o.w = pack2(s[ch + 6][n], s[ch + 7][n]);
            *(uint4*)&D[(size_t)(nb + n) * K_DIM + kb + ch] = o;
        }
    } else if (blockIdx.x < 1024) {
        const int idx = blockIdx.x * 256 + tid;
        const float* sp = x + (size_t)idx * 8;
        float4 a = *(const float4*)sp;
        float4 b = *(const float4*)(sp + 4);
        uint4 o;
        o.x = pack2(a.x, a.y); o.y = pack2(a.z, a.w);
        o.z = pack2(b.x, b.y); o.w = pack2(b.z, b.w);
        *(uint4*)&g_xh[(size_t)idx * 8] = o;
    }
}

// ---------------- fp16 GEMM: ldmatrix + 4-stage cp.async, BK=32 ----------------
// C[M,N] = A[M,K'] @ W' + bias over numCh k32-chunks; A,BT k-contig fp16.
// Block 128x128, 256 thr, 8 warps 2x4, warp tile 64x32.
// Tile row: 64B data + 16B pad (stride 80 -> LDSM phases conflict-free:
// banks 20r+c mod 32 distinct over any 8 rows). One wait+barrier per k32.
#define TBUF  10240              // 128 * 80
#define STG_B (2 * TBUF)         // 20480 (A then B)
#define SMEMB (4 * STG_B)        // 81920

__device__ __forceinline__ void gemm_body(const __half* __restrict__ A,
                                          const __half* __restrict__ BT,
                                          const float* __restrict__ bias,
                                          float* __restrict__ C, int numCh)
{
    extern __shared__ __align__(16) char sm[];
    const uint32_t sb = smem_u32(sm);

    const int tid  = threadIdx.x;
    const int lane = tid & 31;
    const int wid  = tid >> 5;
    const int wm   = wid >> 2;
    const int wn   = wid & 3;
    const int lr   = lane >> 2;
    const int lc   = lane & 3;
    const int bm   = blockIdx.y * 128;
    const int bn   = blockIdx.x * 128;

    // cp.async: 2 threads/row; thread hh covers bytes [hh*32, hh*32+32) of the
    // 64B row chunk -> two 16B pieces. Chunk kt advances 32 halves.
    const int rr = tid >> 1, hh = tid & 1;
    const __half* Asrc = A  + (size_t)(bm + rr) * K_DIM + hh * 16;
    const __half* Bsrc = BT + (size_t)(bn + rr) * K_DIM + hh * 16;
    const uint32_t aOff = (uint32_t)(rr * 80 + hh * 32);
    const uint32_t bOff = TBUF + aOff;

    // ldmatrix lane offsets (within a k16 sub-step; sub-step 1 at +32B)
    const uint32_t laneA = (uint32_t)((lane & 15) * 80 + (lane >> 4) * 16);
    const uint32_t laneB = (uint32_t)(((lane & 7) + ((lane >> 4) << 3)) * 80
                                      + ((lane >> 3) & 1) * 16);

    float c[4][4][4];
    #pragma unroll
    for (int i = 0; i < 4; i++)
        #pragma unroll
        for (int j = 0; j < 4; j++)
            #pragma unroll
            for (int r = 0; r < 4; r++) c[i][j][r] = 0.0f;

    #pragma unroll
    for (int p = 0; p < 3; p++) {
        const uint32_t base = sb + p * STG_B;
        CP_ASYNC16(base + aOff,      Asrc + (size_t)p * 32);
        CP_ASYNC16(base + aOff + 16, Asrc + (size_t)p * 32 + 8);
        CP_ASYNC16(base + bOff,      Bsrc + (size_t)p * 32);
        CP_ASYNC16(base + bOff + 16, Bsrc + (size_t)p * 32 + 8);
        CP_COMMIT();
    }

    for (int kt = 0; kt < numCh; kt++) {
        const int s = kt & 3;
        if (kt < numCh - 2)       { CP_WAIT2(); }
        else if (kt == numCh - 2) { CP_WAIT1(); }
        else                      { CP_WAIT0(); }
        __syncthreads();

        if (kt + 3 < numCh) {
            const uint32_t base = sb + ((kt + 3) & 3) * STG_B;
            CP_ASYNC16(base + aOff,      Asrc + (size_t)(kt + 3) * 32);
            CP_ASYNC16(base + aOff + 16, Asrc + (size_t)(kt + 3) * 32 + 8);
            CP_ASYNC16(base + bOff,      Bsrc + (size_t)(kt + 3) * 32);
            CP_ASYNC16(base + bOff + 16, Bsrc + (size_t)(kt + 3) * 32 + 8);
            CP_COMMIT();
        }

        const uint32_t stg = sb + s * STG_B;
        #pragma unroll
        for (int ks = 0; ks < 2; ks++) {
            const uint32_t aAdr = stg + wm * 5120 + laneA + ks * 32;
            const uint32_t bAdr = stg + TBUF + wn * 2560 + laneB + ks * 32;
            unsigned af[4][4], bf[4][2];
            LDSM4(af[0][0], af[0][1], af[0][2], af[0][3], aAdr);
            LDSM4(af[1][0], af[1][1], af[1][2], af[1][3], aAdr + 1280);
            LDSM4(af[2][0], af[2][1], af[2][2], af[2][3], aAdr + 2560);
            LDSM4(af[3][0], af[3][1], af[3][2], af[3][3], aAdr + 3840);
            LDSM4(bf[0][0], bf[0][1], bf[1][0], bf[1][1], bAdr);
            LDSM4(bf[2][0], bf[2][1], bf[3][0], bf[3][1], bAdr + 1280);
            #pragma unroll
            for (int i = 0; i < 4; i++)
                #pragma unroll
                for (int j = 0; j < 4; j++)
                    mma_f16(c[i][j], af[i][0], af[i][1], af[i][2], af[i][3],
                            bf[j][0], bf[j][1]);
        }
    }

    #pragma unroll
    for (int i = 0; i < 4; i++) {
        const int row0 = bm + wm * 64 + i * 16 + lr;
        #pragma unroll
        for (int j = 0; j < 4; j++) {
            const int col = bn + wn * 32 + j * 8 + 2 * lc;
            float2 bb = *(const float2*)(bias + col);
            float2 r0, r1;
            r0.x = c[i][j][0] + bb.x;  r0.y = c[i][j][1] + bb.y;
            r1.x = c[i][j][2] + bb.x;  r1.y = c[i][j][3] + bb.y;
            *(float2*)&C[(size_t)row0 * N_DIM + col]       = r0;
            *(float2*)&C[(size_t)(row0 + 8) * N_DIM + col] = r1;
        }
    }
}

__global__ __launch_bounds__(256, 2)
void qkv_gemm(const float* __restrict__ bq, const float* __restrict__ bk,
              const float* __restrict__ bv)
{
    const int z = blockIdx.z;
    const float* bias = (z == 0) ? bq : (z == 1) ? bk : bv;
    float* C = (z == 0) ? g_q : (z == 1) ? g_k : g_v;
    gemm_body(g_xh, g_whT + (size_t)z * WSZ, bias, C, 64);
}

// Split-K=2: z=0 -> K[0,1024) + bias -> g_q; z=1 -> K[1024,2048) + 0 -> g_k.
// Deterministic two-operand reduce afterwards.
__global__ __launch_bounds__(256, 2)
void o_gemm(const float* __restrict__ bo)
{
    const int z = blockIdx.z;
    const __half* A  = g_att + (size_t)z * 1024;
    const __half* BT = g_whT + (size_t)3 * WSZ + (size_t)z * 1024;
    gemm_body(A, BT, z == 0 ? bo : g_zero, z == 0 ? g_q : g_k, 32);
}

__global__ __launch_bounds__(256)
void reduce_o(float* __restrict__ out)
{
    const int i = (blockIdx.x * 256 + threadIdx.x) * 4;
    float4 a = *(const float4*)&g_q[i];
    float4 b = *(const float4*)&g_k[i];
    a.x += b.x; a.y += b.y; a.z += b.z; a.w += b.w;
    *(float4*)&out[i] = a;
}

// ---------------- fast exp ----------------
__device__ __forceinline__ float fast_exp(float x)
{
    float z  = x * 1.4426950408889634f;
    float fi = z + 12582912.0f;
    int   n  = __float_as_int(fi) - 0x4B400000;
    float f  = z - (fi - 12582912.0f);
    float p  = 1.3333558146e-3f;
    p = fmaf(p, f, 9.6181291918e-3f);
    p = fmaf(p, f, 5.5504108664e-2f);
    p = fmaf(p, f, 2.4022650695e-1f);
    p = fmaf(p, f, 6.9314718056e-1f);
    p = fmaf(p, f, 1.0f);
    return __int_as_float(__float_as_int(p) + (n << 23));
}

// ---------------- per-(b,s) head-mixing attention ----------------
// 64 threads/block; thread t handles heads t, t+64, t+128, t+192 of row m.
// phase_shift is analytically dead (cos^2+sin^2=1; imaginary softmax discarded).
__global__ __launch_bounds__(64)
void attention_kernel()
{
    const int m = blockIdx.x;
    const int t = threadIdx.x;   // 0..63

    __shared__ float ks[N_DIM];
    __shared__ float vs[N_DIM];

    const float* qrow = g_q + (size_t)m * N_DIM;
    const float* krow = g_k + (size_t)m * N_DIM;
    const float* vrow = g_v + (size_t)m * N_DIM;

    #pragma unroll
    for (int i = 0; i < 8; i++) {
        const int o4 = (i * 64 + t) * 4;
        *(float4*)&ks[o4] = *(const float4*)&krow[o4];
        *(float4*)&vs[o4] = *(const float4*)&vrow[o4];
    }

    const float scale = 0.35355339059327373f;   // 1/sqrt(8)
    ull q01[4], q23[4], q45[4], q67[4];
    #pragma unroll
    for (int hh = 0; hh < 4; hh++) {
        const int h = t + hh * 64;
        float4 a = *(const float4*)&qrow[h * 8];
        float4 b = *(const float4*)&qrow[h * 8 + 4];
        q01[hh] = pk2f(a.x * scale, a.y * scale);
        q23[hh] = pk2f(a.z * scale, a.w * scale);
        q45[hh] = pk2f(b.x * scale, b.y * scale);
        q67[hh] = pk2f(b.z * scale, b.w * scale);
    }

    __syncthreads();

    float sum[4] = {0.f, 0.f, 0.f, 0.f};
    ull o01[4] = {0, 0, 0, 0};
    ull o23[4] = {0, 0, 0, 0};
    ull o45[4] = {0, 0, 0, 0};
    ull o67[4] = {0, 0, 0, 0};

    #pragma unroll 2
    for (int g = 0; g < HEADS; g++) {
        const ulonglong2 ka = *(const ulonglong2*)&ks[g * 8];
        const ulonglong2 kb = *(const ulonglong2*)&ks[g * 8 + 4];
        const ulonglong2 va = *(const ulonglong2*)&vs[g * 8];
        const ulonglong2 vb = *(const ulonglong2*)&vs[g * 8 + 4];
        #pragma unroll
        for (int hh = 0; hh < 4; hh++) {
            ull s2;
            MULX2(s2, q01[hh], ka.x);
            FMAX2(s2, q23[hh], ka.y, s2);
            FMAX2(s2, q45[hh], kb.x, s2);
            FMAX2(s2, q67[hh], kb.y, s2);
            float sx, sy; UPKX2(sx, sy, s2);
            const float p = fast_exp(sx + sy);
            sum[hh] += p;
            const ull pp = pk2f(p, p);
            FMAX2(o01[hh], pp, va.x, o01[hh]);
            FMAX2(o23[hh], pp, va.y, o23[hh]);
            FMAX2(o45[hh], pp, vb.x, o45[hh]);
            FMAX2(o67[hh], pp, vb.y, o67[hh]);
        }
    }

    #pragma unroll
    for (int hh = 0; hh < 4; hh++) {
        const float inv = 1.0f / sum[hh];
        const ull iv = pk2f(inv, inv);
        MULX2(o01[hh], o01[hh], iv);
        MULX2(o23[hh], o23[hh], iv);
        MULX2(o45[hh], o45[hh], iv);
        MULX2(o67[hh], o67[hh], iv);
        float a, b;
        uint4 st;
        UPKX2(a, b, o01[hh]); st.x = pack2(a, b);
        UPKX2(a, b, o23[hh]); st.y = pack2(a, b);
        UPKX2(a, b, o45[hh]); st.z = pack2(a, b);
        UPKX2(a, b, o67[hh]); st.w = pack2(a, b);
        const int h = t + hh * 64;
        *(uint4*)&g_att[(size_t)m * N_DIM + h * 8] = st;
    }
}

// ---------------- launch ----------------
extern "C" void kernel_launch(void* const* d_in, const int* in_sizes, int n_in,
                              void* d_out, int out_size)
{
    const float* x  = (const float*)d_in[0];
    // d_in[1] = phase_shift: dead.
    const float* Wq = (const float*)d_in[2];
    const float* bq = (const float*)d_in[3];
    const float* Wk = (const float*)d_in[4];
    const float* bk = (const float*)d_in[5];
    const float* Wv = (const float*)d_in[6];
    const float* bv = (const float*)d_in[7];
    const float* Wo = (const float*)d_in[8];
    const float* bo = (const float*)d_in[9];
    float* out = (float*)d_out;

    cudaFuncSetAttribute(qkv_gemm, cudaFuncAttributeMaxDynamicSharedMemorySize, SMEMB);
    cudaFuncSetAttribute(o_gemm,   cudaFuncAttributeMaxDynamicSharedMemorySize, SMEMB);

    cvt_all<<<dim3(1024, 5), dim3(32, 8)>>>(x, Wq, Wk, Wv, Wo);
    qkv_gemm<<<dim3(N_DIM / 128, M_DIM / 128, 3), 256, SMEMB>>>(bq, bk, bv);
    attention_kernel<<<M_DIM, 64>>>();
    o_gemm<<<dim3(N_DIM / 128, M_DIM / 128, 2), 256, SMEMB>>>(bo);
    reduce_o<<<2048, 256>>>(out);
}